// round 3
// baseline (speedup 1.0000x reference)
#include <cuda_runtime.h>
#include <math.h>

#define BATCH   4
#define SLEN    2048
#define DDIM    1024
#define OUTD    1024

// Scratch (device globals: allocation-free rule).
__device__ float g_Q [BATCH * SLEN * OUTD];   // 32 MB
__device__ float g_K [BATCH * SLEN * OUTD];   // 32 MB
__device__ float g_V [BATCH * SLEN * OUTD];   // 32 MB
__device__ float g_Sc[BATCH * SLEN * SLEN];   // 64 MB (scores / softmax probs)

// Buffer selector codes: resolve scratch addresses in DEVICE code so that
// kernel_launch contains kernel launches only.
#define BUF_EXT 0
#define BUF_Q   1
#define BUF_K   2
#define BUF_V   3
#define BUF_SC  4

__device__ __forceinline__ float* buf_resolve(int code, const float* ext) {
    switch (code) {
        case BUF_Q:  return g_Q;
        case BUF_K:  return g_K;
        case BUF_V:  return g_V;
        case BUF_SC: return g_Sc;
        default:     return (float*)ext;
    }
}

// ---------------------------------------------------------------------------
// Tiled SGEMM: C[M,N] = alpha * A[M,K] @ op(B),  op(B)=B[K,N] (NN) or B[N,K]^T (NT)
// 128x128 block tile, K-tile 8, 256 threads, 8x8 per-thread accumulator.
// Software-pipelined: K-tile k+1 is prefetched to registers during compute of k.
// blockIdx.z batches via strides. All dims assumed multiples of tile sizes.
// ---------------------------------------------------------------------------
template<bool TRANS_B>
__global__ void __launch_bounds__(256, 1)
sgemm_kernel(const float* __restrict__ Aext, int Acode,
             const float* __restrict__ Bext, int Bcode,
             float* __restrict__ Cext, int Ccode,
             int M, int N, int K,
             long sA, long sB, long sC, float alpha)
{
    const float* A = buf_resolve(Acode, Aext) + (long)blockIdx.z * sA;
    const float* B = buf_resolve(Bcode, Bext) + (long)blockIdx.z * sB;
    float*       C = buf_resolve(Ccode, Cext) + (long)blockIdx.z * sC;

    __shared__ float As[8][128];
    __shared__ float Bs[8][128];

    const int tid = threadIdx.x;
    const int m0 = blockIdx.y * 128;
    const int n0 = blockIdx.x * 128;
    const int tr = tid >> 4;        // 0..15
    const int tc = tid & 15;        // 0..15

    // A-tile (and NT B-tile) loader indices: 128 rows x 8 cols
    const int ar = tid >> 1;        // 0..127
    const int ac = (tid & 1) * 4;   // 0 or 4
    // NN B-tile loader indices: 8 rows x 128 cols
    const int br = tid >> 5;        // 0..7
    const int bc = (tid & 31) * 4;  // 0..124

    float acc[8][8];
#pragma unroll
    for (int i = 0; i < 8; i++)
#pragma unroll
        for (int j = 0; j < 8; j++) acc[i][j] = 0.0f;

    // ---- load K-tile 0 into shared ----
    float4 av = *(const float4*)&A[(long)(m0 + ar) * K + ac];
    float4 bv;
    if (TRANS_B) bv = *(const float4*)&B[(long)(n0 + ar) * K + ac];
    else         bv = *(const float4*)&B[(long)br * N + n0 + bc];

    As[ac + 0][ar] = av.x; As[ac + 1][ar] = av.y;
    As[ac + 2][ar] = av.z; As[ac + 3][ar] = av.w;
    if (TRANS_B) {
        Bs[ac + 0][ar] = bv.x; Bs[ac + 1][ar] = bv.y;
        Bs[ac + 2][ar] = bv.z; Bs[ac + 3][ar] = bv.w;
    } else {
        *(float4*)&Bs[br][bc] = bv;
    }
    __syncthreads();

    for (int k0 = 0; k0 < K; k0 += 8) {
        // ---- prefetch K-tile k0+8 into registers (overlaps with FMAs) ----
        const bool have_next = (k0 + 8) < K;
        if (have_next) {
            av = *(const float4*)&A[(long)(m0 + ar) * K + (k0 + 8) + ac];
            if (TRANS_B) bv = *(const float4*)&B[(long)(n0 + ar) * K + (k0 + 8) + ac];
            else         bv = *(const float4*)&B[(long)(k0 + 8 + br) * N + n0 + bc];
        }

        // ---- compute on current shared tile ----
#pragma unroll
        for (int kk = 0; kk < 8; kk++) {
            float4 a0 = *(const float4*)&As[kk][tr * 8];
            float4 a1 = *(const float4*)&As[kk][tr * 8 + 4];
            float4 b0 = *(const float4*)&Bs[kk][tc * 8];
            float4 b1 = *(const float4*)&Bs[kk][tc * 8 + 4];
            float a[8] = {a0.x, a0.y, a0.z, a0.w, a1.x, a1.y, a1.z, a1.w};
            float b[8] = {b0.x, b0.y, b0.z, b0.w, b1.x, b1.y, b1.z, b1.w};
#pragma unroll
            for (int i = 0; i < 8; i++)
#pragma unroll
                for (int j = 0; j < 8; j++)
                    acc[i][j] = fmaf(a[i], b[j], acc[i][j]);
        }
        __syncthreads();

        // ---- commit prefetched registers to shared ----
        if (have_next) {
            As[ac + 0][ar] = av.x; As[ac + 1][ar] = av.y;
            As[ac + 2][ar] = av.z; As[ac + 3][ar] = av.w;
            if (TRANS_B) {
                Bs[ac + 0][ar] = bv.x; Bs[ac + 1][ar] = bv.y;
                Bs[ac + 2][ar] = bv.z; Bs[ac + 3][ar] = bv.w;
            } else {
                *(float4*)&Bs[br][bc] = bv;
            }
            __syncthreads();
        }
    }

#pragma unroll
    for (int i = 0; i < 8; i++) {
        long row = (long)(m0 + tr * 8 + i);
        float4 o0, o1;
        o0.x = alpha * acc[i][0]; o0.y = alpha * acc[i][1];
        o0.z = alpha * acc[i][2]; o0.w = alpha * acc[i][3];
        o1.x = alpha * acc[i][4]; o1.y = alpha * acc[i][5];
        o1.z = alpha * acc[i][6]; o1.w = alpha * acc[i][7];
        *(float4*)&C[row * N + n0 + tc * 8]     = o0;
        *(float4*)&C[row * N + n0 + tc * 8 + 4] = o1;
    }
}

// ---------------------------------------------------------------------------
// Row softmax over g_Sc: one block (256 threads) per row of length `cols`.
// ---------------------------------------------------------------------------
__global__ void __launch_bounds__(256, 4)
softmax_kernel(int cols)
{
    float* Sc = g_Sc;
    const long base = (long)blockIdx.x * cols;
    const int tid = threadIdx.x;
    __shared__ float red[8];

    // max
    float lmax = -3.0e38f;
    for (int i = tid; i < cols; i += 256)
        lmax = fmaxf(lmax, Sc[base + i]);
#pragma unroll
    for (int o = 16; o > 0; o >>= 1)
        lmax = fmaxf(lmax, __shfl_xor_sync(0xFFFFFFFFu, lmax, o));
    if ((tid & 31) == 0) red[tid >> 5] = lmax;
    __syncthreads();
    float rmax = red[0];
#pragma unroll
    for (int w = 1; w < 8; w++) rmax = fmaxf(rmax, red[w]);
    __syncthreads();

    // exp + sum
    float lsum = 0.0f;
    for (int i = tid; i < cols; i += 256) {
        float e = __expf(Sc[base + i] - rmax);
        Sc[base + i] = e;
        lsum += e;
    }
#pragma unroll
    for (int o = 16; o > 0; o >>= 1)
        lsum += __shfl_xor_sync(0xFFFFFFFFu, lsum, o);
    if ((tid & 31) == 0) red[tid >> 5] = lsum;
    __syncthreads();
    float rsum = 0.0f;
#pragma unroll
    for (int w = 0; w < 8; w++) rsum += red[w];

    const float inv = 1.0f / rsum;
    for (int i = tid; i < cols; i += 256)
        Sc[base + i] *= inv;
}

// ---------------------------------------------------------------------------
// Launch: QKV proj (3x NN GEMM) -> scores (NT GEMM, scaled) -> softmax -> AV
// kernel_launch contains ONLY kernel launches (graph-capture-safe).
// ---------------------------------------------------------------------------
extern "C" void kernel_launch(void* const* d_in, const int* in_sizes, int n_in,
                              void* d_out, int out_size)
{
    const float* x = (const float*)d_in[0];   // [4,2048,1024]
    const float* y = (const float*)d_in[1];   // [4,2048,1024]
    const float* w = (const float*)d_in[2];   // [3,1024,1024]
    float* out = (float*)d_out;               // [4,2048,1024]

    const int  M   = BATCH * SLEN;            // 8192
    const long WSZ = (long)DDIM * OUTD;       // 1M
    dim3 blk(256);

    // QKV projections: [8192,1024] @ [1024,1024]
    dim3 gproj(OUTD / 128, M / 128, 1);       // (8, 64)
    sgemm_kernel<false><<<gproj, blk>>>(x, BUF_EXT, w + 0 * WSZ, BUF_EXT,
                                        nullptr, BUF_Q, M, OUTD, DDIM, 0, 0, 0, 1.0f);
    sgemm_kernel<false><<<gproj, blk>>>(x, BUF_EXT, w + 1 * WSZ, BUF_EXT,
                                        nullptr, BUF_K, M, OUTD, DDIM, 0, 0, 0, 1.0f);
    sgemm_kernel<false><<<gproj, blk>>>(y, BUF_EXT, w + 2 * WSZ, BUF_EXT,
                                        nullptr, BUF_V, M, OUTD, DDIM, 0, 0, 0, 1.0f);

    // Scores: per batch, [2048,1024] @ [2048,1024]^T * (1/sqrt(1024))
    dim3 gsc(SLEN / 128, SLEN / 128, BATCH);  // (16, 16, 4)
    sgemm_kernel<true><<<gsc, blk>>>(nullptr, BUF_Q, nullptr, BUF_K,
                                     nullptr, BUF_SC, SLEN, SLEN, OUTD,
                                     (long)SLEN * OUTD, (long)SLEN * OUTD,
                                     (long)SLEN * SLEN, 0.03125f);

    // Softmax over rows of scores
    softmax_kernel<<<BATCH * SLEN, 256>>>(SLEN);

    // Output: per batch, [2048,2048] @ [2048,1024]
    dim3 gav(OUTD / 128, SLEN / 128, BATCH);  // (8, 16, 4)
    sgemm_kernel<false><<<gav, blk>>>(nullptr, BUF_SC, nullptr, BUF_V,
                                      out, BUF_EXT, SLEN, OUTD, SLEN,
                                      (long)SLEN * SLEN, (long)SLEN * OUTD,
                                      (long)SLEN * OUTD, 1.0f);
}

// round 7
// speedup vs baseline: 2.2564x; 2.2564x over previous
#include <cuda_runtime.h>
#include <cuda_bf16.h>
#include <math.h>

#define BATCH   4
#define SLEN    2048
#define DDIM    1024
#define OUTD    1024
#define MSUM    (BATCH * SLEN)          // 8192

// ---------------------------------------------------------------------------
// Device-global scratch (allocation-free rule). bf16 hi/lo plane pairs.
// ---------------------------------------------------------------------------
__device__ __align__(256) __nv_bfloat16 g_XH[MSUM * DDIM],  g_XL[MSUM * DDIM];
__device__ __align__(256) __nv_bfloat16 g_YH[MSUM * DDIM],  g_YL[MSUM * DDIM];
__device__ __align__(256) __nv_bfloat16 g_WTH[3 * OUTD * DDIM], g_WTL[3 * OUTD * DDIM]; // W^T planes
__device__ __align__(256) __nv_bfloat16 g_QH[MSUM * OUTD],  g_QL[MSUM * OUTD];
__device__ __align__(256) __nv_bfloat16 g_KH[MSUM * OUTD],  g_KL[MSUM * OUTD];
__device__ __align__(256) __nv_bfloat16 g_VTH[BATCH * OUTD * SLEN], g_VTL[BATCH * OUTD * SLEN]; // V^T
__device__ __align__(256) __nv_bfloat16 g_PH[BATCH * SLEN * SLEN],  g_PL[BATCH * SLEN * SLEN];  // probs
__device__ __align__(256) float g_Sc[BATCH * SLEN * SLEN];  // fp32 scores (64MB)

#define C_XH 1
#define C_XL 2
#define C_YH 3
#define C_YL 4
#define C_WTH 5
#define C_WTL 6
#define C_QH 7
#define C_QL 8
#define C_KH 9
#define C_KL 10
#define C_VTH 11
#define C_VTL 12
#define C_PH 13
#define C_PL 14

__device__ __forceinline__ __nv_bfloat16* bbuf(int code) {
    switch (code) {
        case C_XH: return g_XH;   case C_XL: return g_XL;
        case C_YH: return g_YH;   case C_YL: return g_YL;
        case C_WTH: return g_WTH; case C_WTL: return g_WTL;
        case C_QH: return g_QH;   case C_QL: return g_QL;
        case C_KH: return g_KH;   case C_KL: return g_KL;
        case C_VTH: return g_VTH; case C_VTL: return g_VTL;
        case C_PH: return g_PH;   case C_PL: return g_PL;
        default: return g_XH;
    }
}

// ---------------------------------------------------------------------------
// Baseline-ISA helpers: cp.async + ldmatrix + mma.sync (sm_80+, works on sm_100)
// ---------------------------------------------------------------------------
__device__ __forceinline__ unsigned smem_u32(const void* p) {
    unsigned a;
    asm("{ .reg .u64 t; cvta.to.shared.u64 t, %1; cvt.u32.u64 %0, t; }" : "=r"(a) : "l"(p));
    return a;
}
#define CP_ASYNC16(dst, src) \
    asm volatile("cp.async.cg.shared.global [%0], [%1], 16;" :: "r"(dst), "l"(src))
#define CP_COMMIT() asm volatile("cp.async.commit_group;")
#define CP_WAIT1()  asm volatile("cp.async.wait_group 1;")

#define LDSM4(r, addr) \
    asm volatile("ldmatrix.sync.aligned.m8n8.x4.shared.b16 {%0,%1,%2,%3}, [%4];" \
        : "=r"((r)[0]), "=r"((r)[1]), "=r"((r)[2]), "=r"((r)[3]) : "r"(addr))
#define LDSM2(r, addr) \
    asm volatile("ldmatrix.sync.aligned.m8n8.x2.shared.b16 {%0,%1}, [%2];" \
        : "=r"((r)[0]), "=r"((r)[1]) : "r"(addr))

#define MMA16816(d, a, b) \
    asm volatile("mma.sync.aligned.m16n8k16.row.col.f32.bf16.bf16.f32 " \
        "{%0,%1,%2,%3}, {%4,%5,%6,%7}, {%8,%9}, {%0,%1,%2,%3};" \
        : "+f"((d)[0]), "+f"((d)[1]), "+f"((d)[2]), "+f"((d)[3]) \
        : "r"((a)[0]), "r"((a)[1]), "r"((a)[2]), "r"((a)[3]), "r"((b)[0]), "r"((b)[1]))

// SMEM tile geometry: rows of 32 bf16 = 64B = 4 chunks of 16B, XOR swizzle.
__device__ __forceinline__ unsigned sw_off(int row, int chunk) {
    return (unsigned)(row * 64 + ((chunk ^ (row & 3)) << 4));
}

// Stage layout: AH[128x32] @0 (8KB), AL @8192, BH[64x32] @16384 (4KB), BL @20480.
#define STAGE_BYTES 24576

// Issue one stage of cp.async loads. i-ranges map uniformly: i0,1->AH i2,3->AL i4->BH i5->BL
__device__ __forceinline__ void issue_stage(
    unsigned sb, int tid,
    const __nv_bfloat16* AH, const __nv_bfloat16* AL,
    const __nv_bfloat16* BH, const __nv_bfloat16* BL,
    long m0, long n0, long k0, int Kfull)
{
#pragma unroll
    for (int i = 0; i < 6; i++) {
        const int q = i * 256 + tid;
        const __nv_bfloat16* src;
        unsigned dst;
        if (q < 1024) {            // A planes: 512 chunks each (128 rows x 4 chunks)
            const int aq = q & 511;
            const int row = aq >> 2, c = aq & 3;
            src = ((q < 512) ? AH : AL) + (m0 + row) * (long)Kfull + k0 + c * 8;
            dst = sb + ((q < 512) ? 0u : 8192u) + sw_off(row, c);
        } else {                   // B planes: 256 chunks each (64 rows x 4 chunks)
            const int aq = q & 255;
            const int row = aq >> 2, c = aq & 3;
            src = ((q < 1280) ? BH : BL) + (n0 + row) * (long)Kfull + k0 + c * 8;
            dst = sb + ((q < 1280) ? 16384u : 20480u) + sw_off(row, c);
        }
        CP_ASYNC16(dst, src);
    }
}

// ---------------------------------------------------------------------------
// Tensor-core GEMM (legacy mma.sync): C[128x64 tile] = A[M,K] @ B[N,K]^T
// hi/lo split: D += Ah*Bh + Ah*Bl + Al*Bh.  EPI: 0=bf16 hi/lo, 1=transposed
// hi/lo (V->V^T), 2=fp32*alpha (optionally into g_Sc).
// 256 threads = 8 warps (4 m x 2 n), warp tile 32x32, Kt=32, double-buffered.
// ---------------------------------------------------------------------------
template<int EPI>
__global__ void __launch_bounds__(256, 1)
mma_gemm(int ahc, int alc, long aoff, long sA,
         int bhc, int blc, long boff, long sB,
         int ohc, int olc, float* of32, int use_sc, long ooff, long sO, int ldo,
         int Kfull, float alpha)
{
    __shared__ __align__(16) char smem[2 * STAGE_BYTES];   // 48KB static
    const unsigned sbase = smem_u32(smem);
    const int tid  = threadIdx.x;
    const int lane = tid & 31;
    const int wid  = tid >> 5;
    const int warp_m = wid >> 1;     // 0..3
    const int warp_n = wid & 1;      // 0..1
    const int z  = blockIdx.z;
    const long m0 = (long)blockIdx.y * 128;
    const long n0 = (long)blockIdx.x * 64;

    const __nv_bfloat16* AH = bbuf(ahc) + aoff + (long)z * sA;
    const __nv_bfloat16* AL = bbuf(alc) + aoff + (long)z * sA;
    const __nv_bfloat16* BH = bbuf(bhc) + boff + (long)z * sB;
    const __nv_bfloat16* BL = bbuf(blc) + boff + (long)z * sB;

    float acc[2][4][4];
#pragma unroll
    for (int mi = 0; mi < 2; mi++)
#pragma unroll
        for (int ni = 0; ni < 4; ni++)
#pragma unroll
            for (int r = 0; r < 4; r++) acc[mi][ni][r] = 0.0f;

    const int nk = Kfull >> 5;   // K-tiles of 32

    issue_stage(sbase,               tid, AH, AL, BH, BL, m0, n0, 0,  Kfull); CP_COMMIT();
    issue_stage(sbase + STAGE_BYTES, tid, AH, AL, BH, BL, m0, n0, 32, Kfull); CP_COMMIT();

    for (int c = 0; c < nk; c++) {
        CP_WAIT1();
        __syncthreads();
        const unsigned sb = sbase + (unsigned)((c & 1) * STAGE_BYTES);

#pragma unroll
        for (int kk2 = 0; kk2 < 2; kk2++) {          // k16 halves of the k32 tile
            const int ck = kk2 * 2;                  // chunk base (k offset / 8)
            unsigned aHf[2][4], aLf[2][4], bHf[4][2], bLf[4][2];
#pragma unroll
            for (int mi = 0; mi < 2; mi++) {
                const int r = warp_m * 32 + mi * 16 + (lane & 15);
                const unsigned off = sw_off(r, ck + (lane >> 4));
                LDSM4(aHf[mi], sb + off);
                LDSM4(aLf[mi], sb + 8192u + off);
            }
#pragma unroll
            for (int ni = 0; ni < 4; ni++) {
                const int rn = warp_n * 32 + ni * 8 + (lane & 7);
                const unsigned off = sw_off(rn, ck + ((lane >> 3) & 1));
                LDSM2(bHf[ni], sb + 16384u + off);
                LDSM2(bLf[ni], sb + 20480u + off);
            }
#pragma unroll
            for (int mi = 0; mi < 2; mi++)
#pragma unroll
                for (int ni = 0; ni < 4; ni++) {
                    MMA16816(acc[mi][ni], aHf[mi], bHf[ni]);
                    MMA16816(acc[mi][ni], aHf[mi], bLf[ni]);
                    MMA16816(acc[mi][ni], aLf[mi], bHf[ni]);
                }
        }
        __syncthreads();
        if (c + 2 < nk)
            issue_stage(sbase + (unsigned)((c & 1) * STAGE_BYTES), tid,
                        AH, AL, BH, BL, m0, n0, (long)(c + 2) * 32, Kfull);
        CP_COMMIT();   // always commit to keep group accounting uniform
    }

    // ---- epilogue: frag element (mi,ni,r) -> row/col within CTA tile ----
#pragma unroll
    for (int mi = 0; mi < 2; mi++)
#pragma unroll
        for (int ni = 0; ni < 4; ni++)
#pragma unroll
            for (int r = 0; r < 4; r++) {
                const int row = warp_m * 32 + mi * 16 + (lane >> 2) + ((r & 2) ? 8 : 0);
                const int col = warp_n * 32 + ni * 8 + ((lane & 3) << 1) + (r & 1);
                const float v = acc[mi][ni][r];
                const long gm = m0 + row;
                if (EPI == 2) {
                    float* O = (use_sc ? g_Sc : of32);
                    O[ooff + (long)z * sO + gm * (long)ldo + n0 + col] = v * alpha;
                } else if (EPI == 0) {
                    __nv_bfloat16* OH = bbuf(ohc);
                    __nv_bfloat16* OL = bbuf(olc);
                    const long a = ooff + (long)z * sO + gm * (long)ldo + n0 + col;
                    const __nv_bfloat16 h = __float2bfloat16(v);
                    OH[a] = h;
                    OL[a] = __float2bfloat16(v - __bfloat162float(h));
                } else {   // EPI == 1: V -> V^T[b][o][s]
                    __nv_bfloat16* OH = bbuf(ohc);
                    __nv_bfloat16* OL = bbuf(olc);
                    const long b = gm >> 11;
                    const long s = gm & (SLEN - 1);
                    const long a = b * (long)OUTD * SLEN + (n0 + col) * (long)SLEN + s;
                    const __nv_bfloat16 h = __float2bfloat16(v);
                    OH[a] = h;
                    OL[a] = __float2bfloat16(v - __bfloat162float(h));
                }
            }
}

// ---------------------------------------------------------------------------
// fp32 -> bf16 hi/lo planes (elementwise)
// ---------------------------------------------------------------------------
__global__ void cvt_hilo(const float* __restrict__ src, int hic, int loc, long n)
{
    __nv_bfloat16* H = bbuf(hic);
    __nv_bfloat16* L = bbuf(loc);
    for (long i = (long)blockIdx.x * blockDim.x + threadIdx.x; i < n;
         i += (long)gridDim.x * blockDim.x) {
        const float v = src[i];
        const __nv_bfloat16 h = __float2bfloat16(v);
        H[i] = h;
        L[i] = __float2bfloat16(v - __bfloat162float(h));
    }
}

// ---------------------------------------------------------------------------
// W[3][K=d][N=o] -> WT[3][o][d] hi/lo planes (tiled transpose)
// ---------------------------------------------------------------------------
__global__ void cvt_w_t(const float* __restrict__ W)
{
    __shared__ float tile[32][33];
    const int z = blockIdx.z;
    const int k0 = blockIdx.x * 32;
    const int n0 = blockIdx.y * 32;
    const int tx = threadIdx.x, ty = threadIdx.y;  // (32, 8)
    const long base = (long)z * DDIM * OUTD;
#pragma unroll
    for (int i = 0; i < 32; i += 8)
        tile[ty + i][tx] = W[base + (long)(k0 + ty + i) * OUTD + n0 + tx];
    __syncthreads();
#pragma unroll
    for (int i = 0; i < 32; i += 8) {
        const float v = tile[tx][ty + i];
        const __nv_bfloat16 h = __float2bfloat16(v);
        const long a = base + (long)(n0 + ty + i) * DDIM + k0 + tx;
        g_WTH[a] = h;
        g_WTL[a] = __float2bfloat16(v - __bfloat162float(h));
    }
}

// ---------------------------------------------------------------------------
// Row softmax over fp32 scores -> bf16 hi/lo prob planes
// ---------------------------------------------------------------------------
__global__ void __launch_bounds__(256, 4)
softmax_cvt()
{
    const long base = (long)blockIdx.x * SLEN;
    const int tid = threadIdx.x;
    __shared__ float red[8];

    float lmax = -3.0e38f;
    for (int i = tid; i < SLEN; i += 256)
        lmax = fmaxf(lmax, g_Sc[base + i]);
#pragma unroll
    for (int o = 16; o > 0; o >>= 1)
        lmax = fmaxf(lmax, __shfl_xor_sync(0xFFFFFFFFu, lmax, o));
    if ((tid & 31) == 0) red[tid >> 5] = lmax;
    __syncthreads();
    float rmax = red[0];
#pragma unroll
    for (int w = 1; w < 8; w++) rmax = fmaxf(rmax, red[w]);
    __syncthreads();

    float lsum = 0.0f;
    for (int i = tid; i < SLEN; i += 256) {
        const float e = __expf(g_Sc[base + i] - rmax);
        g_Sc[base + i] = e;
        lsum += e;
    }
#pragma unroll
    for (int o = 16; o > 0; o >>= 1)
        lsum += __shfl_xor_sync(0xFFFFFFFFu, lsum, o);
    if ((tid & 31) == 0) red[tid >> 5] = lsum;
    __syncthreads();
    float rsum = 0.0f;
#pragma unroll
    for (int w = 0; w < 8; w++) rsum += red[w];

    const float inv = 1.0f / rsum;
    for (int i = tid; i < SLEN; i += 256) {
        const float p = g_Sc[base + i] * inv;
        const __nv_bfloat16 h = __float2bfloat16(p);
        g_PH[base + i] = h;
        g_PL[base + i] = __float2bfloat16(p - __bfloat162float(h));
    }
}

// ---------------------------------------------------------------------------
// Launch: only kernel launches (graph-capture-safe; no attribute calls).
// ---------------------------------------------------------------------------
extern "C" void kernel_launch(void* const* d_in, const int* in_sizes, int n_in,
                              void* d_out, int out_size)
{
    const float* x = (const float*)d_in[0];   // [4,2048,1024]
    const float* y = (const float*)d_in[1];   // [4,2048,1024]
    const float* w = (const float*)d_in[2];   // [3,1024,1024]
    float* out = (float*)d_out;               // [4,2048,1024]

    // fp32 -> bf16 hi/lo conversions
    cvt_hilo<<<1024, 256>>>(x, C_XH, C_XL, (long)MSUM * DDIM);
    cvt_hilo<<<1024, 256>>>(y, C_YH, C_YL, (long)MSUM * DDIM);
    cvt_w_t<<<dim3(DDIM / 32, OUTD / 32, 3), dim3(32, 8)>>>(w);

    const long WSL = (long)OUTD * DDIM;  // 1M per weight slice
    dim3 blk(256);

    // Projections: [8192,1024] @ W^T slice, CTA tile 128x64
    dim3 gproj(OUTD / 64, MSUM / 128, 1);      // (16, 64)
    mma_gemm<0><<<gproj, blk>>>(C_XH, C_XL, 0, 0,
                                C_WTH, C_WTL, 0 * WSL, 0,
                                C_QH, C_QL, nullptr, 0, 0, 0, OUTD, DDIM, 1.0f);
    mma_gemm<0><<<gproj, blk>>>(C_XH, C_XL, 0, 0,
                                C_WTH, C_WTL, 1 * WSL, 0,
                                C_KH, C_KL, nullptr, 0, 0, 0, OUTD, DDIM, 1.0f);
    mma_gemm<1><<<gproj, blk>>>(C_YH, C_YL, 0, 0,
                                C_WTH, C_WTL, 2 * WSL, 0,
                                C_VTH, C_VTL, nullptr, 0, 0, 0, 0, DDIM, 1.0f);

    // Scores: per batch Q @ K^T * (1/32) -> fp32 g_Sc
    dim3 gsc(SLEN / 64, SLEN / 128, BATCH);    // (32, 16, 4)
    mma_gemm<2><<<gsc, blk>>>(C_QH, C_QL, 0, (long)SLEN * OUTD,
                              C_KH, C_KL, 0, (long)SLEN * OUTD,
                              0, 0, nullptr, 1, 0, (long)SLEN * SLEN, SLEN,
                              OUTD, 0.03125f);

    // Softmax + prob hi/lo planes
    softmax_cvt<<<BATCH * SLEN, 256>>>();

    // AV: per batch P @ (V^T)^T -> out fp32
    dim3 gav(OUTD / 64, SLEN / 128, BATCH);    // (16, 16, 4)
    mma_gemm<2><<<gav, blk>>>(C_PH, C_PL, 0, (long)SLEN * SLEN,
                              C_VTH, C_VTL, 0, (long)OUTD * SLEN,
                              0, 0, out, 0, 0, (long)SLEN * OUTD, OUTD,
                              SLEN, 1.0f);
}